// round 2
// baseline (speedup 1.0000x reference)
#include <cuda_runtime.h>

// Problem constants
#define S_LEN 2048
#define DM    1024
#define NH    16
#define DKH   64
#define BATCH 4
#define MROWS (BATCH * S_LEN)   // 8192

// Scratch (device globals: no cudaMalloc allowed)
__device__ float g_qs[(size_t)BATCH * NH * S_LEN * DKH];  // [B,H,S,dk]
__device__ float g_ks[(size_t)BATCH * NH * S_LEN * DKH];
__device__ float g_vs[(size_t)BATCH * NH * S_LEN * DKH];
__device__ float g_ao[(size_t)MROWS * DM];                // [B,S,D] attention output

// ---------------------------------------------------------------------------
// SGEMM NT core: C[M,N] = A[M,K] * B[N,K]^T  (both row-major, K contiguous)
// 128x128 block tile, BK=16, 256 threads, 8x8 microtile per thread.
// Computes acc[8][8]; caller-specific epilogue.
// ---------------------------------------------------------------------------

// QKV projection with fused head-split store: out[((b*NH+h)*S + s)*dk + d]
__global__ __launch_bounds__(256) void qkv_proj(
    const float* __restrict__ q_in, const float* __restrict__ k_in,
    const float* __restrict__ v_in,
    const float* __restrict__ wq, const float* __restrict__ wk,
    const float* __restrict__ wv)
{
    __shared__ float As[16][128];
    __shared__ float Bs[16][128];

    const float* A;
    const float* Bm;
    float* Out;
    if (blockIdx.z == 0)      { A = q_in; Bm = wq; Out = g_qs; }
    else if (blockIdx.z == 1) { A = k_in; Bm = wk; Out = g_ks; }
    else                      { A = v_in; Bm = wv; Out = g_vs; }

    const int tid = threadIdx.x;
    const int tx = tid & 15, ty = tid >> 4;
    const int m0 = blockIdx.y * 128, n0 = blockIdx.x * 128;

    float acc[8][8];
#pragma unroll
    for (int i = 0; i < 8; ++i)
#pragma unroll
        for (int j = 0; j < 8; ++j) acc[i][j] = 0.f;

    for (int k0 = 0; k0 < DM; k0 += 16) {
#pragma unroll
        for (int i = 0; i < 2; ++i) {
            int f = tid + i * 256;            // 0..511 (float4 id)
            int r = f >> 2;                   // 0..127
            int c = (f & 3) << 2;             // 0,4,8,12
            float4 va = *(const float4*)(A  + (size_t)(m0 + r) * DM + k0 + c);
            As[c + 0][r] = va.x; As[c + 1][r] = va.y;
            As[c + 2][r] = va.z; As[c + 3][r] = va.w;
            float4 vb = *(const float4*)(Bm + (size_t)(n0 + r) * DM + k0 + c);
            Bs[c + 0][r] = vb.x; Bs[c + 1][r] = vb.y;
            Bs[c + 2][r] = vb.z; Bs[c + 3][r] = vb.w;
        }
        __syncthreads();
#pragma unroll
        for (int kk = 0; kk < 16; ++kk) {
            float a[8], b[8];
            *(float4*)(a)     = *(const float4*)&As[kk][ty * 4];
            *(float4*)(a + 4) = *(const float4*)&As[kk][64 + ty * 4];
            *(float4*)(b)     = *(const float4*)&Bs[kk][tx * 4];
            *(float4*)(b + 4) = *(const float4*)&Bs[kk][64 + tx * 4];
#pragma unroll
            for (int i = 0; i < 8; ++i)
#pragma unroll
                for (int j = 0; j < 8; ++j) acc[i][j] += a[i] * b[j];
        }
        __syncthreads();
    }

    // Epilogue: head-split store (4 consecutive cols from 4-aligned never cross a head)
#pragma unroll
    for (int i = 0; i < 8; ++i) {
        int m = m0 + ((i < 4) ? (ty * 4 + i) : (64 + ty * 4 + (i - 4)));
        int b = m >> 11;          // / S_LEN
        int s = m & (S_LEN - 1);
#pragma unroll
        for (int jq = 0; jq < 2; ++jq) {
            int n = n0 + jq * 64 + tx * 4;
            int h = n >> 6;
            int d = n & 63;
            float4 v = make_float4(acc[i][jq * 4 + 0], acc[i][jq * 4 + 1],
                                   acc[i][jq * 4 + 2], acc[i][jq * 4 + 3]);
            *(float4*)(Out + ((size_t)((b * NH + h) * S_LEN + s)) * DKH + d) = v;
        }
    }
}

// Output projection: out[M,N] = g_ao[M,K] * wo[N,K]^T
__global__ __launch_bounds__(256) void out_proj(
    const float* __restrict__ wo, float* __restrict__ Cout)
{
    __shared__ float As[16][128];
    __shared__ float Bs[16][128];

    const float* A = g_ao;
    const int tid = threadIdx.x;
    const int tx = tid & 15, ty = tid >> 4;
    const int m0 = blockIdx.y * 128, n0 = blockIdx.x * 128;

    float acc[8][8];
#pragma unroll
    for (int i = 0; i < 8; ++i)
#pragma unroll
        for (int j = 0; j < 8; ++j) acc[i][j] = 0.f;

    for (int k0 = 0; k0 < DM; k0 += 16) {
#pragma unroll
        for (int i = 0; i < 2; ++i) {
            int f = tid + i * 256;
            int r = f >> 2;
            int c = (f & 3) << 2;
            float4 va = *(const float4*)(A  + (size_t)(m0 + r) * DM + k0 + c);
            As[c + 0][r] = va.x; As[c + 1][r] = va.y;
            As[c + 2][r] = va.z; As[c + 3][r] = va.w;
            float4 vb = *(const float4*)(wo + (size_t)(n0 + r) * DM + k0 + c);
            Bs[c + 0][r] = vb.x; Bs[c + 1][r] = vb.y;
            Bs[c + 2][r] = vb.z; Bs[c + 3][r] = vb.w;
        }
        __syncthreads();
#pragma unroll
        for (int kk = 0; kk < 16; ++kk) {
            float a[8], b[8];
            *(float4*)(a)     = *(const float4*)&As[kk][ty * 4];
            *(float4*)(a + 4) = *(const float4*)&As[kk][64 + ty * 4];
            *(float4*)(b)     = *(const float4*)&Bs[kk][tx * 4];
            *(float4*)(b + 4) = *(const float4*)&Bs[kk][64 + tx * 4];
#pragma unroll
            for (int i = 0; i < 8; ++i)
#pragma unroll
                for (int j = 0; j < 8; ++j) acc[i][j] += a[i] * b[j];
        }
        __syncthreads();
    }

#pragma unroll
    for (int i = 0; i < 8; ++i) {
        int m = m0 + ((i < 4) ? (ty * 4 + i) : (64 + ty * 4 + (i - 4)));
#pragma unroll
        for (int jq = 0; jq < 2; ++jq) {
            int n = n0 + jq * 64 + tx * 4;
            float4 v = make_float4(acc[i][jq * 4 + 0], acc[i][jq * 4 + 1],
                                   acc[i][jq * 4 + 2], acc[i][jq * 4 + 3]);
            *(float4*)(Cout + (size_t)m * DM + n) = v;
        }
    }
}

// ---------------------------------------------------------------------------
// Flash attention (causal), fp32. One thread per query row, 128 rows/CTA.
// K/V tiles 64x64 in smem; all lanes of a warp read the SAME K/V element
// (different q-rows) -> smem broadcast, conflict-free, float4 => 4 FMA / LDS.
// Online softmax in 16-wide key chunks.
// ---------------------------------------------------------------------------
__global__ __launch_bounds__(128) void flash_attn()
{
    __shared__ float Ks[64][64];
    __shared__ float Vs[64][64];

    const int tid = threadIdx.x;
    const int qt  = blockIdx.x;            // query tile (128 rows)
    const int bh  = blockIdx.y;            // b*NH + h
    const int q0  = qt * 128;
    const int srow = q0 + tid;             // this thread's query row in [0,S)

    // Load q row into registers, fold softmax scale 1/sqrt(dk)=0.125
    float q[DKH];
    {
        const float* Qr = g_qs + ((size_t)bh * S_LEN + srow) * DKH;
#pragma unroll
        for (int i = 0; i < 16; ++i) {
            float4 v = *(const float4*)(Qr + 4 * i);
            q[4 * i + 0] = v.x * 0.125f;
            q[4 * i + 1] = v.y * 0.125f;
            q[4 * i + 2] = v.z * 0.125f;
            q[4 * i + 3] = v.w * 0.125f;
        }
    }

    float o[DKH];
#pragma unroll
    for (int d = 0; d < DKH; ++d) o[d] = 0.f;
    float m = -1e30f, l = 0.f;

    const int ntiles = qt * 2 + 2;         // kv tiles of 64 up to q0+128

    for (int t = 0; t < ntiles; ++t) {
        const int j0 = t * 64;
        const float* Kb = g_ks + (size_t)bh * S_LEN * DKH + (size_t)j0 * DKH;
        const float* Vb = g_vs + (size_t)bh * S_LEN * DKH + (size_t)j0 * DKH;
#pragma unroll
        for (int i = 0; i < 8; ++i) {
            int f = tid + i * 128;          // 0..1023 float4 ids
            int r = f >> 4;
            int c = (f & 15) << 2;
            *(float4*)&Ks[r][c] = *(const float4*)(Kb + r * DKH + c);
            *(float4*)&Vs[r][c] = *(const float4*)(Vb + r * DKH + c);
        }
        __syncthreads();

        const bool full = (j0 + 63 <= q0);  // uniform per block

#pragma unroll
        for (int jc = 0; jc < 64; jc += 16) {
            float sc[16];
#pragma unroll
            for (int jj = 0; jj < 16; ++jj) {
                const float4* kp = (const float4*)(&Ks[jc + jj][0]);
                float a = 0.f;
#pragma unroll
                for (int d4 = 0; d4 < 16; ++d4) {
                    float4 kv = kp[d4];
                    a += q[4 * d4 + 0] * kv.x;
                    a += q[4 * d4 + 1] * kv.y;
                    a += q[4 * d4 + 2] * kv.z;
                    a += q[4 * d4 + 3] * kv.w;
                }
                sc[jj] = a;
            }
            if (!full) {
#pragma unroll
                for (int jj = 0; jj < 16; ++jj)
                    if (j0 + jc + jj > srow) sc[jj] = -1e30f;
            }
            float mnew = m;
#pragma unroll
            for (int jj = 0; jj < 16; ++jj) mnew = fmaxf(mnew, sc[jj]);
            float corr = __expf(m - mnew);
            l *= corr;
#pragma unroll
            for (int d = 0; d < DKH; ++d) o[d] *= corr;
#pragma unroll
            for (int jj = 0; jj < 16; ++jj) {
                float p = __expf(sc[jj] - mnew);
                l += p;
                const float4* vp = (const float4*)(&Vs[jc + jj][0]);
#pragma unroll
                for (int d4 = 0; d4 < 16; ++d4) {
                    float4 vv = vp[d4];
                    o[4 * d4 + 0] += p * vv.x;
                    o[4 * d4 + 1] += p * vv.y;
                    o[4 * d4 + 2] += p * vv.z;
                    o[4 * d4 + 3] += p * vv.w;
                }
            }
            m = mnew;
        }
        __syncthreads();
    }

    const float inv = 1.f / l;
    const int b = bh >> 4;
    const int h = bh & 15;
    float* op = g_ao + ((size_t)(b * S_LEN + srow)) * DM + h * DKH;
#pragma unroll
    for (int i = 0; i < 16; ++i) {
        float4 v = make_float4(o[4 * i + 0] * inv, o[4 * i + 1] * inv,
                               o[4 * i + 2] * inv, o[4 * i + 3] * inv);
        *(float4*)(op + 4 * i) = v;
    }
}

// ---------------------------------------------------------------------------
extern "C" void kernel_launch(void* const* d_in, const int* in_sizes, int n_in,
                              void* d_out, int out_size)
{
    const float* q_in = (const float*)d_in[0];
    const float* k_in = (const float*)d_in[1];
    const float* v_in = (const float*)d_in[2];
    // d_in[3] = causal mask (structure known; not needed)
    const float* wq = (const float*)d_in[4];
    const float* wk = (const float*)d_in[5];
    const float* wv = (const float*)d_in[6];
    const float* wo = (const float*)d_in[7];
    float* out = (float*)d_out;

    qkv_proj<<<dim3(DM / 128, MROWS / 128, 3), 256>>>(q_in, k_in, v_in, wq, wk, wv);
    flash_attn<<<dim3(S_LEN / 128, BATCH * NH), 128>>>();
    out_proj<<<dim3(DM / 128, MROWS / 128), 256>>>(wo, out);
}

// round 3
// speedup vs baseline: 1.0041x; 1.0041x over previous
#include <cuda_runtime.h>

// Problem constants
#define S_LEN 2048
#define DM    1024
#define NH    16
#define DKH   64
#define BATCH 4
#define MROWS (BATCH * S_LEN)   // 8192

// Scratch (device globals: no cudaMalloc allowed)
__device__ float g_qs[(size_t)BATCH * NH * S_LEN * DKH];  // [B,H,S,dk]
__device__ float g_ks[(size_t)BATCH * NH * S_LEN * DKH];
__device__ float g_vs[(size_t)BATCH * NH * S_LEN * DKH];
__device__ float g_ao[(size_t)MROWS * DM];                // [B,S,D] attention output

// ---------------------------------------------------------------------------
// SGEMM NT core: C[M,N] = A[M,K] * B[N,K]^T  (both row-major, K contiguous)
// 128x128 block tile, BK=16, 256 threads, 8x8 microtile per thread.
// Computes acc[8][8]; caller-specific epilogue.
// ---------------------------------------------------------------------------

// QKV projection with fused head-split store: out[((b*NH+h)*S + s)*dk + d]
__global__ __launch_bounds__(256) void qkv_proj(
    const float* __restrict__ q_in, const float* __restrict__ k_in,
    const float* __restrict__ v_in,
    const float* __restrict__ wq, const float* __restrict__ wk,
    const float* __restrict__ wv)
{
    __shared__ float As[16][128];
    __shared__ float Bs[16][128];

    const float* A;
    const float* Bm;
    float* Out;
    if (blockIdx.z == 0)      { A = q_in; Bm = wq; Out = g_qs; }
    else if (blockIdx.z == 1) { A = k_in; Bm = wk; Out = g_ks; }
    else                      { A = v_in; Bm = wv; Out = g_vs; }

    const int tid = threadIdx.x;
    const int tx = tid & 15, ty = tid >> 4;
    const int m0 = blockIdx.y * 128, n0 = blockIdx.x * 128;

    float acc[8][8];
#pragma unroll
    for (int i = 0; i < 8; ++i)
#pragma unroll
        for (int j = 0; j < 8; ++j) acc[i][j] = 0.f;

    for (int k0 = 0; k0 < DM; k0 += 16) {
#pragma unroll
        for (int i = 0; i < 2; ++i) {
            int f = tid + i * 256;            // 0..511 (float4 id)
            int r = f >> 2;                   // 0..127
            int c = (f & 3) << 2;             // 0,4,8,12
            float4 va = *(const float4*)(A  + (size_t)(m0 + r) * DM + k0 + c);
            As[c + 0][r] = va.x; As[c + 1][r] = va.y;
            As[c + 2][r] = va.z; As[c + 3][r] = va.w;
            float4 vb = *(const float4*)(Bm + (size_t)(n0 + r) * DM + k0 + c);
            Bs[c + 0][r] = vb.x; Bs[c + 1][r] = vb.y;
            Bs[c + 2][r] = vb.z; Bs[c + 3][r] = vb.w;
        }
        __syncthreads();
#pragma unroll
        for (int kk = 0; kk < 16; ++kk) {
            float a[8], b[8];
            *(float4*)(a)     = *(const float4*)&As[kk][ty * 4];
            *(float4*)(a + 4) = *(const float4*)&As[kk][64 + ty * 4];
            *(float4*)(b)     = *(const float4*)&Bs[kk][tx * 4];
            *(float4*)(b + 4) = *(const float4*)&Bs[kk][64 + tx * 4];
#pragma unroll
            for (int i = 0; i < 8; ++i)
#pragma unroll
                for (int j = 0; j < 8; ++j) acc[i][j] += a[i] * b[j];
        }
        __syncthreads();
    }

    // Epilogue: head-split store (4 consecutive cols from 4-aligned never cross a head)
#pragma unroll
    for (int i = 0; i < 8; ++i) {
        int m = m0 + ((i < 4) ? (ty * 4 + i) : (64 + ty * 4 + (i - 4)));
        int b = m >> 11;          // / S_LEN
        int s = m & (S_LEN - 1);
#pragma unroll
        for (int jq = 0; jq < 2; ++jq) {
            int n = n0 + jq * 64 + tx * 4;
            int h = n >> 6;
            int d = n & 63;
            float4 v = make_float4(acc[i][jq * 4 + 0], acc[i][jq * 4 + 1],
                                   acc[i][jq * 4 + 2], acc[i][jq * 4 + 3]);
            *(float4*)(Out + ((size_t)((b * NH + h) * S_LEN + s)) * DKH + d) = v;
        }
    }
}

// Output projection: out[M,N] = g_ao[M,K] * wo[N,K]^T
__global__ __launch_bounds__(256) void out_proj(
    const float* __restrict__ wo, float* __restrict__ Cout)
{
    __shared__ float As[16][128];
    __shared__ float Bs[16][128];

    const float* A = g_ao;
    const int tid = threadIdx.x;
    const int tx = tid & 15, ty = tid >> 4;
    const int m0 = blockIdx.y * 128, n0 = blockIdx.x * 128;

    float acc[8][8];
#pragma unroll
    for (int i = 0; i < 8; ++i)
#pragma unroll
        for (int j = 0; j < 8; ++j) acc[i][j] = 0.f;

    for (int k0 = 0; k0 < DM; k0 += 16) {
#pragma unroll
        for (int i = 0; i < 2; ++i) {
            int f = tid + i * 256;
            int r = f >> 2;
            int c = (f & 3) << 2;
            float4 va = *(const float4*)(A  + (size_t)(m0 + r) * DM + k0 + c);
            As[c + 0][r] = va.x; As[c + 1][r] = va.y;
            As[c + 2][r] = va.z; As[c + 3][r] = va.w;
            float4 vb = *(const float4*)(wo + (size_t)(n0 + r) * DM + k0 + c);
            Bs[c + 0][r] = vb.x; Bs[c + 1][r] = vb.y;
            Bs[c + 2][r] = vb.z; Bs[c + 3][r] = vb.w;
        }
        __syncthreads();
#pragma unroll
        for (int kk = 0; kk < 16; ++kk) {
            float a[8], b[8];
            *(float4*)(a)     = *(const float4*)&As[kk][ty * 4];
            *(float4*)(a + 4) = *(const float4*)&As[kk][64 + ty * 4];
            *(float4*)(b)     = *(const float4*)&Bs[kk][tx * 4];
            *(float4*)(b + 4) = *(const float4*)&Bs[kk][64 + tx * 4];
#pragma unroll
            for (int i = 0; i < 8; ++i)
#pragma unroll
                for (int j = 0; j < 8; ++j) acc[i][j] += a[i] * b[j];
        }
        __syncthreads();
    }

#pragma unroll
    for (int i = 0; i < 8; ++i) {
        int m = m0 + ((i < 4) ? (ty * 4 + i) : (64 + ty * 4 + (i - 4)));
#pragma unroll
        for (int jq = 0; jq < 2; ++jq) {
            int n = n0 + jq * 64 + tx * 4;
            float4 v = make_float4(acc[i][jq * 4 + 0], acc[i][jq * 4 + 1],
                                   acc[i][jq * 4 + 2], acc[i][jq * 4 + 3]);
            *(float4*)(Cout + (size_t)m * DM + n) = v;
        }
    }
}

// ---------------------------------------------------------------------------
// Flash attention (causal), fp32. One thread per query row, 128 rows/CTA.
// K/V tiles 64x64 in smem; all lanes of a warp read the SAME K/V element
// (different q-rows) -> smem broadcast, conflict-free, float4 => 4 FMA / LDS.
// Online softmax in 16-wide key chunks.
// ---------------------------------------------------------------------------
__global__ __launch_bounds__(128) void flash_attn()
{
    __shared__ float Ks[64][64];
    __shared__ float Vs[64][64];

    const int tid = threadIdx.x;
    const int qt  = blockIdx.x;            // query tile (128 rows)
    const int bh  = blockIdx.y;            // b*NH + h
    const int q0  = qt * 128;
    const int srow = q0 + tid;             // this thread's query row in [0,S)

    // Load q row into registers, fold softmax scale 1/sqrt(dk)=0.125
    float q[DKH];
    {
        const float* Qr = g_qs + ((size_t)bh * S_LEN + srow) * DKH;
#pragma unroll
        for (int i = 0; i < 16; ++i) {
            float4 v = *(const float4*)(Qr + 4 * i);
            q[4 * i + 0] = v.x * 0.125f;
            q[4 * i + 1] = v.y * 0.125f;
            q[4 * i + 2] = v.z * 0.125f;
            q[4 * i + 3] = v.w * 0.125f;
        }
    }

    float o[DKH];
#pragma unroll
    for (int d = 0; d < DKH; ++d) o[d] = 0.f;
    float m = -1e30f, l = 0.f;

    const int ntiles = qt * 2 + 2;         // kv tiles of 64 up to q0+128

    for (int t = 0; t < ntiles; ++t) {
        const int j0 = t * 64;
        const float* Kb = g_ks + (size_t)bh * S_LEN * DKH + (size_t)j0 * DKH;
        const float* Vb = g_vs + (size_t)bh * S_LEN * DKH + (size_t)j0 * DKH;
#pragma unroll
        for (int i = 0; i < 8; ++i) {
            int f = tid + i * 128;          // 0..1023 float4 ids
            int r = f >> 4;
            int c = (f & 15) << 2;
            *(float4*)&Ks[r][c] = *(const float4*)(Kb + r * DKH + c);
            *(float4*)&Vs[r][c] = *(const float4*)(Vb + r * DKH + c);
        }
        __syncthreads();

        const bool full = (j0 + 63 <= q0);  // uniform per block

#pragma unroll
        for (int jc = 0; jc < 64; jc += 16) {
            float sc[16];
#pragma unroll
            for (int jj = 0; jj < 16; ++jj) {
                const float4* kp = (const float4*)(&Ks[jc + jj][0]);
                float a = 0.f;
#pragma unroll
                for (int d4 = 0; d4 < 16; ++d4) {
                    float4 kv = kp[d4];
                    a += q[4 * d4 + 0] * kv.x;
                    a += q[4 * d4 + 1] * kv.y;
                    a += q[4 * d4 + 2] * kv.z;
                    a += q[4 * d4 + 3] * kv.w;
                }
                sc[jj] = a;
            }
            if (!full) {
#pragma unroll
                for (int jj = 0; jj < 16; ++jj)
                    if (j0 + jc + jj > srow) sc[jj] = -1e30f;
            }
            float mnew = m;
#pragma unroll
            for (int jj = 0; jj < 16; ++jj) mnew = fmaxf(mnew, sc[jj]);
            float corr = __expf(m - mnew);
            l *= corr;
#pragma unroll
            for (int d = 0; d < DKH; ++d) o[d] *= corr;
#pragma unroll
            for (int jj = 0; jj < 16; ++jj) {
                float p = __expf(sc[jj] - mnew);
                l += p;
                const float4* vp = (const float4*)(&Vs[jc + jj][0]);
#pragma unroll
                for (int d4 = 0; d4 < 16; ++d4) {
                    float4 vv = vp[d4];
                    o[4 * d4 + 0] += p * vv.x;
                    o[4 * d4 + 1] += p * vv.y;
                    o[4 * d4 + 2] += p * vv.z;
                    o[4 * d4 + 3] += p * vv.w;
                }
            }
            m = mnew;
        }
        __syncthreads();
    }

    const float inv = 1.f / l;
    const int b = bh >> 4;
    const int h = bh & 15;
    float* op = g_ao + ((size_t)(b * S_LEN + srow)) * DM + h * DKH;
#pragma unroll
    for (int i = 0; i < 16; ++i) {
        float4 v = make_float4(o[4 * i + 0] * inv, o[4 * i + 1] * inv,
                               o[4 * i + 2] * inv, o[4 * i + 3] * inv);
        *(float4*)(op + 4 * i) = v;
    }
}

// ---------------------------------------------------------------------------
extern "C" void kernel_launch(void* const* d_in, const int* in_sizes, int n_in,
                              void* d_out, int out_size)
{
    const float* q_in = (const float*)d_in[0];
    const float* k_in = (const float*)d_in[1];
    const float* v_in = (const float*)d_in[2];
    // d_in[3] = causal mask (structure known; not needed)
    const float* wq = (const float*)d_in[4];
    const float* wk = (const float*)d_in[5];
    const float* wv = (const float*)d_in[6];
    const float* wo = (const float*)d_in[7];
    float* out = (float*)d_out;

    qkv_proj<<<dim3(DM / 128, MROWS / 128, 3), 256>>>(q_in, k_in, v_in, wq, wk, wv);
    flash_attn<<<dim3(S_LEN / 128, BATCH * NH), 128>>>();
    out_proj<<<dim3(DM / 128, MROWS / 128), 256>>>(wo, out);
}